// round 16
// baseline (speedup 1.0000x reference)
#include <cuda_runtime.h>
#include <cuda_fp16.h>
#include <cstdint>

#define B_SZ   2
#define LQ     4096
#define LKV    1024
#define DMODEL 512
#define HEADS  8
#define DHEAD  64
#define SPAN   64
#define STRIDE 4

#define MQ (B_SZ * LQ)    // 8192
#define MK (B_SZ * LKV)   // 2048

// ---------------- scratch (all single fp16 intermediates) ----------------
__device__ __half g_Qp [MQ * DMODEL];
__device__ __half g_Kp [MK * DMODEL];
__device__ __half g_Vp [MK * DMODEL];
__device__ __half g_ctx[MQ * DMODEL];
__device__ __half g_Wt [4 * DMODEL * DMODEL];

// ---------------- helpers ----------------
__device__ __forceinline__ uint32_t smem_u32(const void* p) {
    uint32_t a;
    asm("{ .reg .u64 t; cvta.to.shared.u64 t, %1; cvt.u32.u64 %0, t; }" : "=r"(a) : "l"(p));
    return a;
}
__device__ __forceinline__ uint32_t pack_h2(float a, float b) {
    __half2 t(__float2half_rn(a), __float2half_rn(b));
    return *(uint32_t*)&t;
}
__device__ __forceinline__ void ldsm_x4(uint32_t* r, uint32_t a) {
    asm volatile("ldmatrix.sync.aligned.m8n8.x4.shared.b16 {%0,%1,%2,%3}, [%4];"
        : "=r"(r[0]), "=r"(r[1]), "=r"(r[2]), "=r"(r[3]) : "r"(a));
}
__device__ __forceinline__ void ldsm_x2(uint32_t* r, uint32_t a) {
    asm volatile("ldmatrix.sync.aligned.m8n8.x2.shared.b16 {%0,%1}, [%2];"
        : "=r"(r[0]), "=r"(r[1]) : "r"(a));
}
__device__ __forceinline__ void ldsm_x2_trans(uint32_t* r, uint32_t a) {
    asm volatile("ldmatrix.sync.aligned.m8n8.x2.trans.shared.b16 {%0,%1}, [%2];"
        : "=r"(r[0]), "=r"(r[1]) : "r"(a));
}
__device__ __forceinline__ void mma_f16(float* c, const uint32_t* a, const uint32_t* b) {
    asm volatile(
        "mma.sync.aligned.m16n8k16.row.col.f32.f16.f16.f32 "
        "{%0,%1,%2,%3}, {%4,%5,%6,%7}, {%8,%9}, {%0,%1,%2,%3};"
        : "+f"(c[0]), "+f"(c[1]), "+f"(c[2]), "+f"(c[3])
        : "r"(a[0]), "r"(a[1]), "r"(a[2]), "r"(a[3]), "r"(b[0]), "r"(b[1]));
}
__device__ __forceinline__ void cp16(uint32_t dst, const void* src) {
    asm volatile("cp.async.cg.shared.global [%0], [%1], 16;" :: "r"(dst), "l"(src));
}
#define CP_COMMIT() asm volatile("cp.async.commit_group;" ::: "memory")
#define CP_WAIT0()  asm volatile("cp.async.wait_group 0;" ::: "memory")
#define CP_WAIT1()  asm volatile("cp.async.wait_group 1;" ::: "memory")

// ---------------- prepass: transpose weights to single fp16 ----------------
__global__ __launch_bounds__(1024) void split_w_kernel(
    const float* __restrict__ W0, const float* __restrict__ W1,
    const float* __restrict__ W2, const float* __restrict__ W3,
    __half* __restrict__ Wt)
{
    __shared__ float t[32][33];
    const int z = blockIdx.z;
    const float* W = (z == 0) ? W0 : (z == 1) ? W1 : (z == 2) ? W2 : W3;
    const int n0 = blockIdx.x * 32, k0 = blockIdx.y * 32;
    const int tx = threadIdx.x, ty = threadIdx.y;
    t[ty][tx] = W[(size_t)(k0 + ty) * DMODEL + n0 + tx];
    __syncthreads();
    size_t o = (size_t)z * DMODEL * DMODEL + (size_t)(n0 + ty) * DMODEL + k0 + tx;
    Wt[o] = __float2half_rn(t[tx][ty]);
}

// ---------------- GEMM params (R12 shape: 128x128 tile, K-chunk 32, 3 stages) ----------------
#define GROWB 80
#define GTSZ  (128 * GROWB)        // 10240
#define NSTG  3
#define STG   (2 * GTSZ)           // 20480 (A | B)
#define GEMM_SMEM (NSTG * STG)     // 61440 -> 2 CTAs/SM
#define NCH   16                   // 512 / 32

// ---------------- proj GEMM: fp32 A (convert+STS pipelined one chunk ahead), ONE barrier/chunk ----
__global__ __launch_bounds__(256, 2) void proj_fused_kernel(
    const float* __restrict__ q, const float* __restrict__ k, const float* __restrict__ v,
    const __half* __restrict__ Wt,
    __half* __restrict__ Qp, __half* __restrict__ Kp, __half* __restrict__ Vp)
{
    const int bid = blockIdx.x;
    const size_t WSZ = (size_t)DMODEL * DMODEL;
    const float* A32; const __half* B; __half* Ch; int t;
    if (bid < 256)      { A32 = q; B = Wt;           Ch = Qp; t = bid; }
    else if (bid < 320) { A32 = k; B = Wt + WSZ;     Ch = Kp; t = bid - 256; }
    else                { A32 = v; B = Wt + 2 * WSZ; Ch = Vp; t = bid - 320; }
    const int row0 = (t >> 2) * 128;
    const int col0 = (t & 3) * 128;

    extern __shared__ char sm[];
    const uint32_t sb = smem_u32(sm);
    const int tid  = threadIdx.x;
    const int wid  = tid >> 5;
    const int lane = tid & 31;
    const int m0 = (wid & 1) * 64;
    const int n0 = (wid >> 1) * 32;

    float acc[4][4][4];
    #pragma unroll
    for (int mi = 0; mi < 4; mi++)
        #pragma unroll
        for (int ni = 0; ni < 4; ni++)
            #pragma unroll
            for (int e = 0; e < 4; e++) acc[mi][ni][e] = 0.0f;

    const uint32_t a_off = (uint32_t)(m0 + (lane & 15)) * GROWB + ((lane >> 4) << 4);
    const uint32_t b_off = (uint32_t)((lane & 7) + ((lane >> 4) & 1) * 8) * GROWB
                         + (((lane >> 3) & 1) << 4);

    const int ir0 = (tid + 0)   >> 2, ic0 = ((tid + 0)   & 3) << 4;
    const int ir1 = (tid + 256) >> 2, ic1 = ((tid + 256) & 3) << 4;

    float ar[2][8];

    auto ldA_regs = [&](int ch) {
        const int kc = ch * 32;
        {
            const float* pa = A32 + (size_t)(row0 + ir0) * DMODEL + kc + (ic0 >> 1);
            float4 x = *(const float4*)pa, y = *(const float4*)(pa + 4);
            ar[0][0]=x.x; ar[0][1]=x.y; ar[0][2]=x.z; ar[0][3]=x.w;
            ar[0][4]=y.x; ar[0][5]=y.y; ar[0][6]=y.z; ar[0][7]=y.w;
        }
        {
            const float* pa = A32 + (size_t)(row0 + ir1) * DMODEL + kc + (ic1 >> 1);
            float4 x = *(const float4*)pa, y = *(const float4*)(pa + 4);
            ar[1][0]=x.x; ar[1][1]=x.y; ar[1][2]=x.z; ar[1][3]=x.w;
            ar[1][4]=y.x; ar[1][5]=y.y; ar[1][6]=y.z; ar[1][7]=y.w;
        }
    };
    auto stsA = [&](int buf) {      // buf MUST already be reduced mod NSTG
        #pragma unroll
        for (int p = 0; p < 2; p++) {
            const int ir = p ? ir1 : ir0;
            const int ic = p ? ic1 : ic0;
            const float* a = ar[p];
            uint4 hi;
            hi.x = pack_h2(a[0], a[1]); hi.y = pack_h2(a[2], a[3]);
            hi.z = pack_h2(a[4], a[5]); hi.w = pack_h2(a[6], a[7]);
            *(uint4*)(sm + (uint32_t)buf * STG + (uint32_t)ir * GROWB + ic) = hi;
        }
    };
    auto issue_cp = [&](int ch, int buf) {
        const uint32_t stg = sb + (uint32_t)buf * STG;
        const size_t kb = (size_t)ch * 64;
        #pragma unroll
        for (int p = 0; p < 2; p++) {
            const int ir = p ? ir1 : ir0;
            const int ic = p ? ic1 : ic0;
            const size_t gb = (size_t)(col0 + ir) * (DMODEL * 2) + kb + ic;
            cp16(stg + GTSZ + (uint32_t)ir * GROWB + ic, (const char*)B + gb);
        }
        CP_COMMIT();
    };

    // prologue: A(0) staged; B(0), B(1) in flight; A regs hold chunk 1
    ldA_regs(0);
    issue_cp(0, 0);
    issue_cp(1, 1);
    stsA(0);
    ldA_regs(1);

    for (int ch = 0; ch < NCH; ch++) {
        if (ch + 1 < NCH) CP_WAIT1(); else CP_WAIT0();
        __syncthreads();   // publishes stsA of chunk ch; B(ch) complete; compute(ch-1) done by all
        if (ch + 1 < NCH) stsA((ch + 1) % NSTG);   // FIXED: modulo. prev reader compute(ch-2) done.
        if (ch + 2 < NCH) { ldA_regs(ch + 2); issue_cp(ch + 2, (ch + 2) % NSTG); }

        const uint32_t stg = sb + (uint32_t)(ch % NSTG) * STG;
        const uint32_t aA = stg + a_off;
        const uint32_t bB = stg + GTSZ + b_off + (uint32_t)n0 * GROWB;

        #pragma unroll
        for (int ks = 0; ks < 2; ks++) {
            const uint32_t ko = (uint32_t)ks * 32;
            uint32_t bf[2][4], af[4][4];
            ldsm_x4(bf[0], bB + ko);
            ldsm_x4(bf[1], bB + (uint32_t)(16 * GROWB) + ko);
            #pragma unroll
            for (int mi = 0; mi < 4; mi++)
                ldsm_x4(af[mi], aA + (uint32_t)(mi * 16) * GROWB + ko);
            #pragma unroll
            for (int nj = 0; nj < 2; nj++)
                #pragma unroll
                for (int mi = 0; mi < 4; mi++) {
                    mma_f16(acc[mi][2 * nj + 0], af[mi], bf[nj] + 0);
                    mma_f16(acc[mi][2 * nj + 1], af[mi], bf[nj] + 2);
                }
        }
    }

    #pragma unroll
    for (int mi = 0; mi < 4; mi++) {
        #pragma unroll
        for (int ni = 0; ni < 4; ni++) {
            const int row = row0 + m0 + mi * 16 + (lane >> 2);
            const int col = col0 + n0 + ni * 8 + (lane & 3) * 2;
            const float* a = acc[mi][ni];
            *(__half2*)&Ch[(size_t)row * DMODEL + col] =
                __half2(__float2half_rn(a[0]), __float2half_rn(a[1]));
            *(__half2*)&Ch[(size_t)(row + 8) * DMODEL + col] =
                __half2(__float2half_rn(a[2]), __float2half_rn(a[3]));
        }
    }
}

// ---------------- outproj GEMM: fp16 A via cp.async, ONE barrier/chunk ----------------
__global__ __launch_bounds__(256, 2) void outproj_kernel(
    const __half* __restrict__ ctx, const __half* __restrict__ Wt,
    float* __restrict__ out)
{
    extern __shared__ char sm[];
    const uint32_t sb = smem_u32(sm);
    const __half* B = Wt + 3 * (size_t)DMODEL * DMODEL;
    const int row0 = blockIdx.y * 128;
    const int col0 = blockIdx.x * 128;
    const int tid  = threadIdx.x;
    const int wid  = tid >> 5;
    const int lane = tid & 31;
    const int m0 = (wid & 1) * 64;
    const int n0 = (wid >> 1) * 32;

    float acc[4][4][4];
    #pragma unroll
    for (int mi = 0; mi < 4; mi++)
        #pragma unroll
        for (int ni = 0; ni < 4; ni++)
            #pragma unroll
            for (int e = 0; e < 4; e++) acc[mi][ni][e] = 0.0f;

    const uint32_t a_off = (uint32_t)(m0 + (lane & 15)) * GROWB + ((lane >> 4) << 4);
    const uint32_t b_off = (uint32_t)((lane & 7) + ((lane >> 4) & 1) * 8) * GROWB
                         + (((lane >> 3) & 1) << 4);

    const int ir0 = (tid + 0)   >> 2, ic0 = ((tid + 0)   & 3) << 4;
    const int ir1 = (tid + 256) >> 2, ic1 = ((tid + 256) & 3) << 4;

    auto issue_cp = [&](int ch, int buf) {
        const uint32_t stg = sb + (uint32_t)buf * STG;
        const size_t kb = (size_t)ch * 64;
        #pragma unroll
        for (int p = 0; p < 2; p++) {
            const int ir = p ? ir1 : ir0;
            const int ic = p ? ic1 : ic0;
            const uint32_t dso = (uint32_t)ir * GROWB + ic;
            cp16(stg + dso,        (const char*)ctx + (size_t)(row0 + ir) * (DMODEL * 2) + kb + ic);
            cp16(stg + GTSZ + dso, (const char*)B   + (size_t)(col0 + ir) * (DMODEL * 2) + kb + ic);
        }
        CP_COMMIT();
    };

    issue_cp(0, 0);
    issue_cp(1, 1);

    for (int ch = 0; ch < NCH; ch++) {
        if (ch + 1 < NCH) CP_WAIT1(); else CP_WAIT0();
        __syncthreads();   // stage ch complete + published; compute(ch-1) done by all
        if (ch + 2 < NCH) issue_cp(ch + 2, (ch + 2) % NSTG);  // prev reader compute(ch-1) done

        const uint32_t stg = sb + (uint32_t)(ch % NSTG) * STG;
        const uint32_t aA = stg + a_off;
        const uint32_t bB = stg + GTSZ + b_off + (uint32_t)n0 * GROWB;

        #pragma unroll
        for (int ks = 0; ks < 2; ks++) {
            const uint32_t ko = (uint32_t)ks * 32;
            uint32_t bf[2][4], af[4][4];
            ldsm_x4(bf[0], bB + ko);
            ldsm_x4(bf[1], bB + (uint32_t)(16 * GROWB) + ko);
            #pragma unroll
            for (int mi = 0; mi < 4; mi++)
                ldsm_x4(af[mi], aA + (uint32_t)(mi * 16) * GROWB + ko);
            #pragma unroll
            for (int nj = 0; nj < 2; nj++)
                #pragma unroll
                for (int mi = 0; mi < 4; mi++) {
                    mma_f16(acc[mi][2 * nj + 0], af[mi], bf[nj] + 0);
                    mma_f16(acc[mi][2 * nj + 1], af[mi], bf[nj] + 2);
                }
        }
    }

    #pragma unroll
    for (int mi = 0; mi < 4; mi++) {
        #pragma unroll
        for (int ni = 0; ni < 4; ni++) {
            const int row = row0 + m0 + mi * 16 + (lane >> 2);
            const int col = col0 + n0 + ni * 8 + (lane & 3) * 2;
            const float* a = acc[mi][ni];
            *(float2*)&out[(size_t)row * DMODEL + col] = make_float2(a[0], a[1]);
            *(float2*)&out[(size_t)(row + 8) * DMODEL + col] = make_float2(a[2], a[3]);
        }
    }
}

// ---------------- tensor-core sparse attention (R12 verbatim) ----------------
#define AROWB 144
#define SQ 0
#define SK (64 * AROWB)
#define SV (96 * AROWB)
#define ATT_SM (128 * AROWB)

__global__ __launch_bounds__(128) void attn_tc_kernel(
    const __half* __restrict__ Qp, const __half* __restrict__ Kp,
    const __half* __restrict__ Vp, __half* __restrict__ ctx)
{
    __shared__ char sm[ATT_SM];
    const uint32_t sb = smem_u32(sm);
    const int c0  = blockIdx.x * 64;
    const int h   = blockIdx.y;
    const int b   = blockIdx.z;
    const int tid = threadIdx.x;
    const int wid = tid >> 5;
    const int lane = tid & 31;

    int jmin = (c0 - (SPAN - 1) + (STRIDE - 1)) >> 2;
    if (jmin < 0) jmin = 0;
    int jmax = (c0 + 63) >> 2;
    if (jmax > LKV - 1) jmax = LKV - 1;
    const int nrows = jmax - jmin + 1;

    for (int u = tid; u < (32 - nrows) * 36; u += 128) {
        const int r = nrows + u / 36, w = u % 36;
        ((uint32_t*)(sm + SV))[r * 36 + w] = 0;
    }
    for (int u = tid; u < 512; u += 128) {
        const int r = u >> 3, cb = (u & 7) << 4;
        const size_t gb = (size_t)(b * LQ + c0 + r) * (DMODEL * 2) + h * DHEAD * 2 + cb;
        *(uint4*)(sm + SQ + r * AROWB + cb) = *(const uint4*)((const char*)Qp + gb);
    }
    for (int u = tid; u < nrows * 8; u += 128) {
        const int r = u >> 3, cb = (u & 7) << 4;
        const size_t gb = (size_t)(b * LKV + jmin + r) * (DMODEL * 2) + h * DHEAD * 2 + cb;
        *(uint4*)(sm + SK + r * AROWB + cb) = *(const uint4*)((const char*)Kp + gb);
        *(uint4*)(sm + SV + r * AROWB + cb) = *(const uint4*)((const char*)Vp + gb);
    }
    __syncthreads();

    float s[4][4];
    #pragma unroll
    for (int ni = 0; ni < 4; ni++)
        #pragma unroll
        for (int e = 0; e < 4; e++) s[ni][e] = 0.0f;

    const uint32_t qa = sb + SQ + (uint32_t)(wid * 16 + (lane & 15)) * AROWB + ((lane >> 4) << 4);
    const uint32_t kb = sb + SK + (uint32_t)(lane & 7) * AROWB + (((lane >> 3) & 1) << 4);
    #pragma unroll
    for (int ks = 0; ks < 4; ks++) {
        const uint32_t ko = (uint32_t)ks * 32;
        uint32_t q4[4], b2[2];
        ldsm_x4(q4, qa + ko);
        #pragma unroll
        for (int ni = 0; ni < 4; ni++) {
            ldsm_x2(b2, kb + (uint32_t)(ni * 8) * AROWB + ko);
            mma_f16(s[ni], q4, b2);
        }
    }

    const int r_lo = c0 + wid * 16 + (lane >> 2);
    const int r_hi = r_lo + 8;
    #pragma unroll
    for (int ni = 0; ni < 4; ni++) {
        #pragma unroll
        for (int e = 0; e < 4; e++) {
            const int col_abs = jmin + ni * 8 + (lane & 3) * 2 + (e & 1);
            const int c = (e < 2) ? r_lo : r_hi;
            const bool valid = (unsigned)(c - 4 * col_abs) < (unsigned)SPAN;
            s[ni][e] = valid ? s[ni][e] * 0.125f : -1e30f;
        }
    }

    float mx0 = -1e30f, mx1 = -1e30f;
    #pragma unroll
    for (int ni = 0; ni < 4; ni++) {
        mx0 = fmaxf(mx0, fmaxf(s[ni][0], s[ni][1]));
        mx1 = fmaxf(mx1, fmaxf(s[ni][2], s[ni][3]));
    }
    mx0 = fmaxf(mx0, __shfl_xor_sync(0xffffffffu, mx0, 1));
    mx0 = fmaxf(mx0, __shfl_xor_sync(0xffffffffu, mx0, 2));
    mx1 = fmaxf(mx1, __shfl_xor_sync(0xffffffffu, mx1, 1));
    mx1 = fmaxf(mx1, __shfl_xor_sync(0xffffffffu, mx1, 2));
    float sum0 = 0.0f, sum1 = 0.0f;
    #pragma unroll
    for (int ni = 0; ni < 4; ni++) {
        s[ni][0] = __expf(s[ni][0] - mx0); sum0 += s[ni][0];
        s[ni][1] = __expf(s[ni][1] - mx0); sum0 += s[ni][1];
        s[ni][2] = __expf(s[ni][2] - mx1); sum1 += s[ni][2];
        s[ni][3] = __expf(s[ni][3] - mx1); sum1 += s[ni][3];
    }
    sum0 += __shfl_xor_sync(0xffffffffu, sum0, 1);
    sum0 += __shfl_xor_sync(0xffffffffu, sum0, 2);
    sum1 += __shfl_xor_sync(0xffffffffu, sum1, 1);
    sum1 += __shfl_xor_sync(0xffffffffu, sum1, 2);
    const float inv0 = 1.0f / sum0, inv1 = 1.0f / sum1;
    #pragma unroll
    for (int ni = 0; ni < 4; ni++) {
        s[ni][0] *= inv0; s[ni][1] *= inv0;
        s[ni][2] *= inv1; s[ni][3] *= inv1;
    }

    uint32_t aP[2][4];
    #pragma unroll
    for (int kc = 0; kc < 2; kc++) {
        #pragma unroll
        for (int hf = 0; hf < 2; hf++) {
            const float* p = s[2 * kc + hf];
            aP[kc][hf * 2 + 0] = pack_h2(p[0], p[1]);
            aP[kc][hf * 2 + 1] = pack_h2(p[2], p[3]);
        }
    }

    float o[8][4];
    #pragma unroll
    for (int ni = 0; ni < 8; ni++)
        #pragma unroll
        for (int e = 0; e < 4; e++) o[ni][e] = 0.0f;
    const uint32_t vrow = (uint32_t)((lane & 7) + ((lane >> 3) & 1) * 8) * AROWB;
    #pragma unroll
    for (int kc = 0; kc < 2; kc++) {
        const uint32_t kro = (uint32_t)(kc * 16) * AROWB;
        #pragma unroll
        for (int ni = 0; ni < 8; ni++) {
            uint32_t b2[2];
            ldsm_x2_trans(b2, sb + SV + kro + vrow + (uint32_t)(ni * 16));
            mma_f16(o[ni], aP[kc], b2);
        }
    }

    #pragma unroll
    for (int ni = 0; ni < 8; ni++) {
        const int col = ni * 8 + (lane & 3) * 2;
        const size_t i0 = (size_t)(b * LQ + r_lo) * DMODEL + h * DHEAD + col;
        const size_t i1 = (size_t)(b * LQ + r_hi) * DMODEL + h * DHEAD + col;
        *(__half2*)&ctx[i0] =
            __half2(__float2half_rn(o[ni][0]), __float2half_rn(o[ni][1]));
        *(__half2*)&ctx[i1] =
            __half2(__float2half_rn(o[ni][2]), __float2half_rn(o[ni][3]));
    }
}

// ---------------- launch ----------------
extern "C" void kernel_launch(void* const* d_in, const int* in_sizes, int n_in,
                              void* d_out, int out_size)
{
    const float* q    = (const float*)d_in[0];
    const float* k    = (const float*)d_in[1];
    const float* v    = (const float*)d_in[2];
    const float* Wq   = (const float*)d_in[3];
    const float* Wk   = (const float*)d_in[4];
    const float* Wv   = (const float*)d_in[5];
    const float* Wout = (const float*)d_in[6];
    float* out = (float*)d_out;

    __half *Qp, *Kp, *Vp, *ctx, *Wt;
    cudaGetSymbolAddress((void**)&Qp,  g_Qp);
    cudaGetSymbolAddress((void**)&Kp,  g_Kp);
    cudaGetSymbolAddress((void**)&Vp,  g_Vp);
    cudaGetSymbolAddress((void**)&ctx, g_ctx);
    cudaGetSymbolAddress((void**)&Wt,  g_Wt);

    cudaFuncSetAttribute(proj_fused_kernel,
                         cudaFuncAttributeMaxDynamicSharedMemorySize, GEMM_SMEM);
    cudaFuncSetAttribute(outproj_kernel,
                         cudaFuncAttributeMaxDynamicSharedMemorySize, GEMM_SMEM);

    split_w_kernel<<<dim3(16, 16, 4), dim3(32, 32)>>>(Wq, Wk, Wv, Wout, Wt);
    proj_fused_kernel<<<384, 256, GEMM_SMEM>>>(q, k, v, Wt, Qp, Kp, Vp);
    attn_tc_kernel<<<dim3(LQ / 64, HEADS, B_SZ), 128>>>(Qp, Kp, Vp, ctx);
    outproj_kernel<<<dim3(4, 64), 256, GEMM_SMEM>>>(ctx, Wt, out);
}

// round 17
// speedup vs baseline: 1.5398x; 1.5398x over previous
#include <cuda_runtime.h>
#include <cuda_fp16.h>
#include <cstdint>

#define B_SZ   2
#define LQ     4096
#define LKV    1024
#define DMODEL 512
#define HEADS  8
#define DHEAD  64
#define SPAN   64
#define STRIDE 4

#define MQ (B_SZ * LQ)    // 8192
#define MK (B_SZ * LKV)   // 2048

// ---------------- scratch (all single fp16 intermediates) ----------------
__device__ __half g_Qp [MQ * DMODEL];
__device__ __half g_Kp [MK * DMODEL];
__device__ __half g_Vp [MK * DMODEL];
__device__ __half g_ctx[MQ * DMODEL];
__device__ __half g_Wt [4 * DMODEL * DMODEL];

// ---------------- helpers ----------------
__device__ __forceinline__ uint32_t smem_u32(const void* p) {
    uint32_t a;
    asm("{ .reg .u64 t; cvta.to.shared.u64 t, %1; cvt.u32.u64 %0, t; }" : "=r"(a) : "l"(p));
    return a;
}
__device__ __forceinline__ uint32_t pack_h2(float a, float b) {
    __half2 t(__float2half_rn(a), __float2half_rn(b));
    return *(uint32_t*)&t;
}
__device__ __forceinline__ void ldsm_x4(uint32_t* r, uint32_t a) {
    asm volatile("ldmatrix.sync.aligned.m8n8.x4.shared.b16 {%0,%1,%2,%3}, [%4];"
        : "=r"(r[0]), "=r"(r[1]), "=r"(r[2]), "=r"(r[3]) : "r"(a));
}
__device__ __forceinline__ void ldsm_x2(uint32_t* r, uint32_t a) {
    asm volatile("ldmatrix.sync.aligned.m8n8.x2.shared.b16 {%0,%1}, [%2];"
        : "=r"(r[0]), "=r"(r[1]) : "r"(a));
}
__device__ __forceinline__ void ldsm_x2_trans(uint32_t* r, uint32_t a) {
    asm volatile("ldmatrix.sync.aligned.m8n8.x2.trans.shared.b16 {%0,%1}, [%2];"
        : "=r"(r[0]), "=r"(r[1]) : "r"(a));
}
__device__ __forceinline__ void mma_f16(float* c, const uint32_t* a, const uint32_t* b) {
    asm volatile(
        "mma.sync.aligned.m16n8k16.row.col.f32.f16.f16.f32 "
        "{%0,%1,%2,%3}, {%4,%5,%6,%7}, {%8,%9}, {%0,%1,%2,%3};"
        : "+f"(c[0]), "+f"(c[1]), "+f"(c[2]), "+f"(c[3])
        : "r"(a[0]), "r"(a[1]), "r"(a[2]), "r"(a[3]), "r"(b[0]), "r"(b[1]));
}
__device__ __forceinline__ void cp16(uint32_t dst, const void* src) {
    asm volatile("cp.async.cg.shared.global [%0], [%1], 16;" :: "r"(dst), "l"(src));
}
#define CP_COMMIT() asm volatile("cp.async.commit_group;" ::: "memory")
#define CP_WAIT0()  asm volatile("cp.async.wait_group 0;" ::: "memory")
#define CP_WAIT1()  asm volatile("cp.async.wait_group 1;" ::: "memory")

// ---------------- prepass: transpose weights to single fp16 ----------------
__global__ __launch_bounds__(1024) void split_w_kernel(
    const float* __restrict__ W0, const float* __restrict__ W1,
    const float* __restrict__ W2, const float* __restrict__ W3,
    __half* __restrict__ Wt)
{
    __shared__ float t[32][33];
    const int z = blockIdx.z;
    const float* W = (z == 0) ? W0 : (z == 1) ? W1 : (z == 2) ? W2 : W3;
    const int n0 = blockIdx.x * 32, k0 = blockIdx.y * 32;
    const int tx = threadIdx.x, ty = threadIdx.y;
    t[ty][tx] = W[(size_t)(k0 + ty) * DMODEL + n0 + tx];
    __syncthreads();
    size_t o = (size_t)z * DMODEL * DMODEL + (size_t)(n0 + ty) * DMODEL + k0 + tx;
    Wt[o] = __float2half_rn(t[tx][ty]);
}

// ---------------- GEMM (R12 verbatim): 128x128 tile, K-chunk 32, 3 stages ----------------
#define GROWB 80
#define GTSZ  (128 * GROWB)        // 10240
#define NSTG  3
#define STG   (2 * GTSZ)           // 20480 (A | B)
#define GEMM_SMEM (NSTG * STG)     // 61440 -> 2 CTAs/SM
#define NCH   16                   // 512 / 32

template<bool AFP32, bool OUT32>
__device__ __forceinline__ void gemm_pipe_tile(
    const float* __restrict__ A32, const __half* __restrict__ A16,
    const __half* __restrict__ B,
    float* __restrict__ Cf, __half* __restrict__ Ch,
    int row0, int col0)
{
    extern __shared__ char sm[];
    const uint32_t sb = smem_u32(sm);
    const int tid  = threadIdx.x;
    const int wid  = tid >> 5;
    const int lane = tid & 31;
    const int m0 = (wid & 1) * 64;
    const int n0 = (wid >> 1) * 32;

    float acc[4][4][4];
    #pragma unroll
    for (int mi = 0; mi < 4; mi++)
        #pragma unroll
        for (int ni = 0; ni < 4; ni++)
            #pragma unroll
            for (int e = 0; e < 4; e++) acc[mi][ni][e] = 0.0f;

    const uint32_t a_off = (uint32_t)(m0 + (lane & 15)) * GROWB + ((lane >> 4) << 4);
    const uint32_t b_off = (uint32_t)((lane & 7) + ((lane >> 4) & 1) * 8) * GROWB
                         + (((lane >> 3) & 1) << 4);

    const int ir0 = (tid + 0)   >> 2, ic0 = ((tid + 0)   & 3) << 4;
    const int ir1 = (tid + 256) >> 2, ic1 = ((tid + 256) & 3) << 4;

    float ar[2][8];

    auto ldA_regs = [&](int ch) {
        if (!AFP32) return;
        const int kc = ch * 32;
        {
            const float* pa = A32 + (size_t)(row0 + ir0) * DMODEL + kc + (ic0 >> 1);
            float4 x = *(const float4*)pa, y = *(const float4*)(pa + 4);
            ar[0][0]=x.x; ar[0][1]=x.y; ar[0][2]=x.z; ar[0][3]=x.w;
            ar[0][4]=y.x; ar[0][5]=y.y; ar[0][6]=y.z; ar[0][7]=y.w;
        }
        {
            const float* pa = A32 + (size_t)(row0 + ir1) * DMODEL + kc + (ic1 >> 1);
            float4 x = *(const float4*)pa, y = *(const float4*)(pa + 4);
            ar[1][0]=x.x; ar[1][1]=x.y; ar[1][2]=x.z; ar[1][3]=x.w;
            ar[1][4]=y.x; ar[1][5]=y.y; ar[1][6]=y.z; ar[1][7]=y.w;
        }
    };
    auto stsA = [&](int buf) {
        if (!AFP32) return;
        #pragma unroll
        for (int p = 0; p < 2; p++) {
            const int ir = p ? ir1 : ir0;
            const int ic = p ? ic1 : ic0;
            const float* a = ar[p];
            uint4 hi;
            hi.x = pack_h2(a[0], a[1]); hi.y = pack_h2(a[2], a[3]);
            hi.z = pack_h2(a[4], a[5]); hi.w = pack_h2(a[6], a[7]);
            *(uint4*)(sm + (uint32_t)buf * STG + (uint32_t)ir * GROWB + ic) = hi;
        }
    };
    auto issue_cp = [&](int ch, int buf) {
        const uint32_t stg = sb + (uint32_t)buf * STG;
        const size_t kb = (size_t)ch * 64;
        #pragma unroll
        for (int p = 0; p < 2; p++) {
            const int ir = p ? ir1 : ir0;
            const int ic = p ? ic1 : ic0;
            const uint32_t dso = (uint32_t)ir * GROWB + ic;
            const size_t gb = (size_t)(col0 + ir) * (DMODEL * 2) + kb + ic;
            cp16(stg + GTSZ + dso, (const char*)B + gb);
            if (!AFP32) {
                const size_t ga = (size_t)(row0 + ir) * (DMODEL * 2) + kb + ic;
                cp16(stg + dso, (const char*)A16 + ga);
            }
        }
        CP_COMMIT();
    };

    ldA_regs(0);
    issue_cp(0, 0);
    issue_cp(1, 1);

    for (int ch = 0; ch < NCH; ch++) {
        if (ch + 1 < NCH) CP_WAIT1(); else CP_WAIT0();
        __syncthreads();
        stsA(ch % NSTG);
        if (AFP32 && ch + 1 < NCH) ldA_regs(ch + 1);
        if (ch + 2 < NCH) issue_cp(ch + 2, (ch + 2) % NSTG);
        if (AFP32) __syncthreads();      // A STS visible to all warps

        const uint32_t stg = sb + (uint32_t)(ch % NSTG) * STG;
        const uint32_t aA = stg + a_off;
        const uint32_t bB = stg + GTSZ + b_off + (uint32_t)n0 * GROWB;

        #pragma unroll
        for (int ks = 0; ks < 2; ks++) {
            const uint32_t ko = (uint32_t)ks * 32;
            uint32_t bf[2][4], af[4][4];
            ldsm_x4(bf[0], bB + ko);
            ldsm_x4(bf[1], bB + (uint32_t)(16 * GROWB) + ko);
            #pragma unroll
            for (int mi = 0; mi < 4; mi++)
                ldsm_x4(af[mi], aA + (uint32_t)(mi * 16) * GROWB + ko);
            #pragma unroll
            for (int nj = 0; nj < 2; nj++)
                #pragma unroll
                for (int mi = 0; mi < 4; mi++) {
                    mma_f16(acc[mi][2 * nj + 0], af[mi], bf[nj] + 0);
                    mma_f16(acc[mi][2 * nj + 1], af[mi], bf[nj] + 2);
                }
        }
        if (!AFP32) __syncthreads();     // buffer stable until all warps done
    }

    #pragma unroll
    for (int mi = 0; mi < 4; mi++) {
        #pragma unroll
        for (int ni = 0; ni < 4; ni++) {
            const int row = row0 + m0 + mi * 16 + (lane >> 2);
            const int col = col0 + n0 + ni * 8 + (lane & 3) * 2;
            const float* a = acc[mi][ni];
            if (OUT32) {
                *(float2*)&Cf[(size_t)row * DMODEL + col] = make_float2(a[0], a[1]);
                *(float2*)&Cf[(size_t)(row + 8) * DMODEL + col] = make_float2(a[2], a[3]);
            } else {
                *(__half2*)&Ch[(size_t)row * DMODEL + col] =
                    __half2(__float2half_rn(a[0]), __float2half_rn(a[1]));
                *(__half2*)&Ch[(size_t)(row + 8) * DMODEL + col] =
                    __half2(__float2half_rn(a[2]), __float2half_rn(a[3]));
            }
        }
    }
}

__global__ __launch_bounds__(256, 2) void proj_fused_kernel(
    const float* __restrict__ q, const float* __restrict__ k, const float* __restrict__ v,
    const __half* __restrict__ Wt,
    __half* __restrict__ Qp, __half* __restrict__ Kp, __half* __restrict__ Vp)
{
    const int bid = blockIdx.x;
    const size_t WSZ = (size_t)DMODEL * DMODEL;
    const float* A; const __half* B; __half* C; int t;
    if (bid < 256)      { A = q; B = Wt;           C = Qp; t = bid; }
    else if (bid < 320) { A = k; B = Wt + WSZ;     C = Kp; t = bid - 256; }
    else                { A = v; B = Wt + 2 * WSZ; C = Vp; t = bid - 320; }
    gemm_pipe_tile<true, false>(A, nullptr, B, nullptr, C,
                                (t >> 2) * 128, (t & 3) * 128);
}

__global__ __launch_bounds__(256, 2) void outproj_kernel(
    const __half* __restrict__ ctx, const __half* __restrict__ Wt,
    float* __restrict__ out)
{
    const size_t WSZ = (size_t)DMODEL * DMODEL;
    gemm_pipe_tile<false, true>(nullptr, ctx, Wt + 3 * WSZ, out, nullptr,
                                blockIdx.y * 128, blockIdx.x * 128);
}

// ---------------- tensor-core sparse attention (R12 + cp.async tile loads) ----------------
#define AROWB 144
#define SQ 0
#define SK (64 * AROWB)
#define SV (96 * AROWB)
#define ATT_SM (128 * AROWB)

__global__ __launch_bounds__(128) void attn_tc_kernel(
    const __half* __restrict__ Qp, const __half* __restrict__ Kp,
    const __half* __restrict__ Vp, __half* __restrict__ ctx)
{
    __shared__ char sm[ATT_SM];
    const uint32_t sb = smem_u32(sm);
    const int c0  = blockIdx.x * 64;
    const int h   = blockIdx.y;
    const int b   = blockIdx.z;
    const int tid = threadIdx.x;
    const int wid = tid >> 5;
    const int lane = tid & 31;

    int jmin = (c0 - (SPAN - 1) + (STRIDE - 1)) >> 2;
    if (jmin < 0) jmin = 0;
    int jmax = (c0 + 63) >> 2;
    if (jmax > LKV - 1) jmax = LKV - 1;
    const int nrows = jmax - jmin + 1;                  // <= 32

    // Q tile via cp.async (64 rows x 128B = 512 segs, 4/thread)
    for (int u = tid; u < 512; u += 128) {
        const int r = u >> 3, cb = (u & 7) << 4;
        const size_t gb = (size_t)(b * LQ + c0 + r) * (DMODEL * 2) + h * DHEAD * 2 + cb;
        cp16(sb + SQ + r * AROWB + cb, (const char*)Qp + gb);
    }
    // K + V window rows via cp.async
    for (int u = tid; u < nrows * 8; u += 128) {
        const int r = u >> 3, cb = (u & 7) << 4;
        const size_t gb = (size_t)(b * LKV + jmin + r) * (DMODEL * 2) + h * DHEAD * 2 + cb;
        cp16(sb + SK + r * AROWB + cb, (const char*)Kp + gb);
        cp16(sb + SV + r * AROWB + cb, (const char*)Vp + gb);
    }
    CP_COMMIT();
    // zero V tail rows (disjoint from cp destinations: rows >= nrows)
    for (int u = tid; u < (32 - nrows) * 36; u += 128) {
        const int r = nrows + u / 36, w = u % 36;
        ((uint32_t*)(sm + SV))[r * 36 + w] = 0;
    }
    CP_WAIT0();
    __syncthreads();

    float s[4][4];
    #pragma unroll
    for (int ni = 0; ni < 4; ni++)
        #pragma unroll
        for (int e = 0; e < 4; e++) s[ni][e] = 0.0f;

    const uint32_t qa = sb + SQ + (uint32_t)(wid * 16 + (lane & 15)) * AROWB + ((lane >> 4) << 4);
    const uint32_t kb = sb + SK + (uint32_t)(lane & 7) * AROWB + (((lane >> 3) & 1) << 4);
    #pragma unroll
    for (int ks = 0; ks < 4; ks++) {
        const uint32_t ko = (uint32_t)ks * 32;
        uint32_t q4[4], b2[2];
        ldsm_x4(q4, qa + ko);
        #pragma unroll
        for (int ni = 0; ni < 4; ni++) {
            ldsm_x2(b2, kb + (uint32_t)(ni * 8) * AROWB + ko);
            mma_f16(s[ni], q4, b2);
        }
    }

    const int r_lo = c0 + wid * 16 + (lane >> 2);
    const int r_hi = r_lo + 8;
    #pragma unroll
    for (int ni = 0; ni < 4; ni++) {
        #pragma unroll
        for (int e = 0; e < 4; e++) {
            const int col_abs = jmin + ni * 8 + (lane & 3) * 2 + (e & 1);
            const int c = (e < 2) ? r_lo : r_hi;
            const bool valid = (unsigned)(c - 4 * col_abs) < (unsigned)SPAN;
            s[ni][e] = valid ? s[ni][e] * 0.125f : -1e30f;
        }
    }

    float mx0 = -1e30f, mx1 = -1e30f;
    #pragma unroll
    for (int ni = 0; ni < 4; ni++) {
        mx0 = fmaxf(mx0, fmaxf(s[ni][0], s[ni][1]));
        mx1 = fmaxf(mx1, fmaxf(s[ni][2], s[ni][3]));
    }
    mx0 = fmaxf(mx0, __shfl_xor_sync(0xffffffffu, mx0, 1));
    mx0 = fmaxf(mx0, __shfl_xor_sync(0xffffffffu, mx0, 2));
    mx1 = fmaxf(mx1, __shfl_xor_sync(0xffffffffu, mx1, 1));
    mx1 = fmaxf(mx1, __shfl_xor_sync(0xffffffffu, mx1, 2));
    float sum0 = 0.0f, sum1 = 0.0f;
    #pragma unroll
    for (int ni = 0; ni < 4; ni++) {
        s[ni][0] = __expf(s[ni][0] - mx0); sum0 += s[ni][0];
        s[ni][1] = __expf(s[ni][1] - mx0); sum0 += s[ni][1];
        s[ni][2] = __expf(s[ni][2] - mx1); sum1 += s[ni][2];
        s[ni][3] = __expf(s[ni][3] - mx1); sum1 += s[ni][3];
    }
    sum0 += __shfl_xor_sync(0xffffffffu, sum0, 1);
    sum0 += __shfl_xor_sync(0xffffffffu, sum0, 2);
    sum1 += __shfl_xor_sync(0xffffffffu, sum1, 1);
    sum1 += __shfl_xor_sync(0xffffffffu, sum1, 2);
    const float inv0 = 1.0f / sum0, inv1 = 1.0f / sum1;
    #pragma unroll
    for (int ni = 0; ni < 4; ni++) {
        s[ni][0] *= inv0; s[ni][1] *= inv0;
        s[ni][2] *= inv1; s[ni][3] *= inv1;
    }

    uint32_t aP[2][4];
    #pragma unroll
    for (int kc = 0; kc < 2; kc++) {
        #pragma unroll
        for (int hf = 0; hf < 2; hf++) {
            const float* p = s[2 * kc + hf];
            aP[kc][hf * 2 + 0] = pack_h2(p[0], p[1]);
            aP[kc][hf * 2 + 1] = pack_h2(p[2], p[3]);
        }
    }

    float o[8][4];
    #pragma unroll
    for (int ni = 0; ni < 8; ni++)
        #pragma unroll
        for (int e = 0; e < 4; e++) o[ni][e] = 0.0f;
    const uint32_t vrow = (uint32_t)((lane & 7) + ((lane >> 3) & 1) * 8) * AROWB;
    #pragma unroll
    for (int kc = 0; kc < 2; kc++) {
        const uint32_t kro = (uint32_t)(kc * 16) * AROWB;
        #pragma unroll
        for (int ni = 0; ni < 8; ni++) {
            uint32_t b2[2];
            ldsm_x2_trans(b2, sb + SV + kro + vrow + (uint32_t)(ni * 16));
            mma_f16(o[ni], aP[kc], b2);
        }
    }

    #pragma unroll
    for (int ni = 0; ni < 8; ni++) {
        const int col = ni * 8 + (lane & 3) * 2;
        const size_t i0 = (size_t)(b * LQ + r_lo) * DMODEL + h * DHEAD + col;
        const size_t i1 = (size_t)(b * LQ + r_hi) * DMODEL + h * DHEAD + col;
        *(__half2*)&ctx[i0] =
            __half2(__float2half_rn(o[ni][0]), __float2half_rn(o[ni][1]));
        *(__half2*)&ctx[i1] =
            __half2(__float2half_rn(o[ni][2]), __float2half_rn(o[ni][3]));
    }
}

// ---------------- launch ----------------
extern "C" void kernel_launch(void* const* d_in, const int* in_sizes, int n_in,
                              void* d_out, int out_size)
{
    const float* q    = (const float*)d_in[0];
    const float* k    = (const float*)d_in[1];
    const float* v    = (const float*)d_in[2];
    const float* Wq   = (const float*)d_in[3];
    const float* Wk   = (const float*)d_in[4];
    const float* Wv   = (const float*)d_in[5];
    const float* Wout = (const float*)d_in[6];
    float* out = (float*)d_out;

    __half *Qp, *Kp, *Vp, *ctx, *Wt;
    cudaGetSymbolAddress((void**)&Qp,  g_Qp);
    cudaGetSymbolAddress((void**)&Kp,  g_Kp);
    cudaGetSymbolAddress((void**)&Vp,  g_Vp);
    cudaGetSymbolAddress((void**)&ctx, g_ctx);
    cudaGetSymbolAddress((void**)&Wt,  g_Wt);

    cudaFuncSetAttribute(proj_fused_kernel,
                         cudaFuncAttributeMaxDynamicSharedMemorySize, GEMM_SMEM);
    cudaFuncSetAttribute(outproj_kernel,
                         cudaFuncAttributeMaxDynamicSharedMemorySize, GEMM_SMEM);

    split_w_kernel<<<dim3(16, 16, 4), dim3(32, 32)>>>(Wq, Wk, Wv, Wout, Wt);
    proj_fused_kernel<<<384, 256, GEMM_SMEM>>>(q, k, v, Wt, Qp, Kp, Vp);
    attn_tc_kernel<<<dim3(LQ / 64, HEADS, B_SZ), 128>>>(Qp, Kp, Vp, ctx);
    outproj_kernel<<<dim3(4, 64), 256, GEMM_SMEM>>>(ctx, Wt, out);
}